// round 6
// baseline (speedup 1.0000x reference)
#include <cuda_runtime.h>

#define NEGF (-1000000000.0f)
#define FULLMASK 0xffffffffu

// Scratch (device globals — no allocation allowed)
__device__ float g_pot[64 * 128 * 128];   // 4 MB: label/augment-maxed span potentials
__device__ float g_goldpart[4096];        // per-block gold partials (64 blocks per batch)
__device__ float g_margin[64];            // per-batch relu(pred - gold)

// ---------------------------------------------------------------------------
// Kernel 1: pot + gold partials. 8 lanes per cell, 4 shuffles per cell.
// Lane r loads float4 r of the 128B cell (lines fully consumed).
// Gold sum is DISTRIBUTED: lane r adds its own-quarter v_lab, lane 0 adds -v0;
// the deterministic block reduction collapses it (no per-cell gold shuffles).
// ---------------------------------------------------------------------------
__global__ void pot_kernel(const float* __restrict__ logits,
                           const int* __restrict__ labels) {
    __shared__ float gred[256];

    int t = threadIdx.x;
    int lane = t & 31;
    int r = lane & 7;                       // lane within 8-group
    int cell0 = blockIdx.x * 256 + (t >> 3) * 8;  // first cell of this group
    const float4* lg4 = reinterpret_cast<const float4*>(logits);

    float goldacc = 0.0f;
    float mypot = 0.0f;
    #pragma unroll
    for (int n = 0; n < 8; ++n) {
        int cell = cell0 + n;
        int lab = labels[cell];
        if (lab < 0) lab = 0;               // jnp.maximum(labels, 0)
        float4 f = lg4[(size_t)cell * 8 + r];
        int l0 = r * 4;
        float a0 = f.x + (float)((l0 + 0) != lab);
        float a1 = f.y + (float)((l0 + 1) != lab);
        float a2 = f.z + (float)((l0 + 2) != lab);
        float a3 = f.w + (float)((l0 + 3) != lab);
        float acc = fmaxf(fmaxf(a0, a1), fmaxf(a2, a3));
        // distributed gold: only my quarter's candidate, only lane 0's -v0
        float gsel = 0.0f;
        gsel = ((l0 + 0) == lab) ? f.x : gsel;
        gsel = ((l0 + 1) == lab) ? f.y : gsel;
        gsel = ((l0 + 2) == lab) ? f.z : gsel;
        gsel = ((l0 + 3) == lab) ? f.w : gsel;
        goldacc += gsel - ((r == 0) ? f.x : 0.0f);
        // 3-shuffle max over the 8-lane group
        acc = fmaxf(acc, __shfl_xor_sync(FULLMASK, acc, 1));
        acc = fmaxf(acc, __shfl_xor_sync(FULLMASK, acc, 2));
        acc = fmaxf(acc, __shfl_xor_sync(FULLMASK, acc, 4));
        // v0 broadcast from group-base lane
        float v0 = __shfl_sync(FULLMASK, f.x, lane & 24);
        if (n == r) mypot = acc - v0;       // lane r owns cell n of its group
    }
    g_pot[cell0 + r] = mypot;               // fully coalesced

    // deterministic block-reduce of gold contributions
    gred[t] = goldacc;
    __syncthreads();
    #pragma unroll
    for (int s = 128; s >= 32; s >>= 1) {
        if (t < s) gred[t] += gred[t + s];
        __syncthreads();
    }
    if (t < 32) {
        float g = gred[t];
        #pragma unroll
        for (int off = 16; off; off >>= 1)
            g += __shfl_xor_sync(FULLMASK, g, off);
        if (t == 0) g_goldpart[blockIdx.x] = g;
    }
}

// ---------------------------------------------------------------------------
// Kernel 2: CKY max-plus, TWO widths per block barrier (64 barriers not 127).
// 512 threads: 4 lanes (q) per row i = t>>2; warp g owns rows 8g..8g+7.
// Phase (w1, w2=w1+1):
//   A : every row computes width w1 (reads: widths <= w1-1, prev phases).
//       Warp also REDUNDANTLY computes boundary row 8g+8 at width w1
//       (slot-7 lanes), keeping the value in registers (bnd).
//   __syncwarp
//   B : every row computes width w2. Its only same-phase reads are
//       R[i][w1] (own row, own warp) and the k=0 E-term = span [i+1, j]
//       width w1: in-warp for slots 0-6; injected from bnd for slot 7.
// Banks: (132*i + k) mod 32 = (4i + q + 4n) mod 32 -> conflict-free.
// ---------------------------------------------------------------------------
extern __shared__ float cky_smem[];

__global__ void cky_kernel(const float* __restrict__ logits,
                           const int* __restrict__ labels) {
    const int S = 132;
    float* R = cky_smem;                    // betaS[i][w]      at R[S*i + w]
    float* E = cky_smem + 128 * S;          // betaE[j][127-w]  at E[S*j+127-w]
    float* P = cky_smem + 256 * S;          // pot[i][j]        at P[S*i + j]
    __shared__ float sh_potfix;

    int b = blockIdx.x;
    int t = threadIdx.x;
    int i = t >> 2;                         // row 0..127
    int q = t & 3;                          // lane within row group
    int slot = i & 7;                       // row slot within warp (0..7)
    int bcell = b * 16384;

    // length: count labels[b,0,j] != -100
    int haslab = (t < 128) ? (labels[bcell + t] != -100) : 0;
    int len = __syncthreads_count(haslab);

    // preload pot into SMEM (coalesced, conflict-free)
    for (int idx = t; idx < 16384; idx += 512)
        P[(idx >> 7) * S + (idx & 127)] = g_pot[bcell + idx];

    // recompute the augmented special cell (b, 0, len-1): channel 0 gets -1e9
    if (t < 32) {
        int j = len - 1;
        int lab = labels[bcell + j];
        if (lab < 0) lab = 0;
        float v = logits[(size_t)(bcell + j) * 32 + t];
        float x = (t == lab) ? v : (v + 1.0f);
        if (t == 0) x += NEGF;
        #pragma unroll
        for (int off = 16; off; off >>= 1)
            x = fmaxf(x, __shfl_xor_sync(FULLMASK, x, off));
        float v0 = __shfl_sync(FULLMASK, v, 0);
        if (t == 0) sh_potfix = x - v0;
    }
    __syncthreads();
    if (t == 0) P[len - 1] = sh_potfix;     // row 0, col len-1
    __syncthreads();

    // width-0 init (diagonal)
    if (q == 0) {
        float d = P[i * S + i];
        R[i * S] = d;                       // betaS[i][0]
        E[i * S + 127] = d;                 // betaE[i][127]
    }
    __syncthreads();

    for (int w1 = 1; w1 < 128; w1 += 2) {
        // ---- sub-step A: width w1 for own row ----
        {
            int j = i + w1;
            float best = NEGF;
            if (j < 128) {
                const float* A  = R + S * i;
                const float* Ee = E + S * j + (128 - w1);
                int k = q;
                for (; k + 12 < w1; k += 16) {
                    float x0 = A[k]      + Ee[k];
                    float x1 = A[k + 4]  + Ee[k + 4];
                    float x2 = A[k + 8]  + Ee[k + 8];
                    float x3 = A[k + 12] + Ee[k + 12];
                    best = fmaxf(best, fmaxf(fmaxf(x0, x1), fmaxf(x2, x3)));
                }
                for (; k < w1; k += 4)
                    best = fmaxf(best, A[k] + Ee[k]);
            }
            best = fmaxf(best, __shfl_xor_sync(FULLMASK, best, 1));
            best = fmaxf(best, __shfl_xor_sync(FULLMASK, best, 2));
            if (j < 128 && q == 0) {
                float v = best + P[S * i + j];
                R[S * i + w1] = v;
                E[S * j + 127 - w1] = v;
            }
        }
        // ---- sub-step A2: redundant boundary row i2 = 8g+8 at width w1 ----
        float bnd = NEGF;
        {
            int i2 = (i & ~7) + 8;          // uniform within warp
            int j2 = i2 + w1;
            bool act = (j2 < 128);          // uniform within warp
            float bb = NEGF;
            if (act && slot == 7) {
                const float* A2  = R + S * i2;
                const float* E2 = E + S * j2 + (128 - w1);
                int k = q;
                for (; k + 12 < w1; k += 16) {
                    float x0 = A2[k]      + E2[k];
                    float x1 = A2[k + 4]  + E2[k + 4];
                    float x2 = A2[k + 8]  + E2[k + 8];
                    float x3 = A2[k + 12] + E2[k + 12];
                    bb = fmaxf(bb, fmaxf(fmaxf(x0, x1), fmaxf(x2, x3)));
                }
                for (; k < w1; k += 4)
                    bb = fmaxf(bb, A2[k] + E2[k]);
            }
            bb = fmaxf(bb, __shfl_xor_sync(FULLMASK, bb, 1));
            bb = fmaxf(bb, __shfl_xor_sync(FULLMASK, bb, 2));
            if (act) bnd = bb + P[S * i2 + j2];
        }
        __syncwarp();
        // ---- sub-step B: width w2 = w1+1 ----
        int w2 = w1 + 1;
        if (w2 < 128) {
            int j = i + w2;
            float best = NEGF;
            if (j < 128) {
                const float* A  = R + S * i;
                const float* Ee = E + S * j + (128 - w2);
                int k = q;
                if (slot == 7 && q == 0) {   // inject boundary value for k=0
                    best = A[0] + bnd;
                    k = 4;
                }
                for (; k + 12 < w2; k += 16) {
                    float x0 = A[k]      + Ee[k];
                    float x1 = A[k + 4]  + Ee[k + 4];
                    float x2 = A[k + 8]  + Ee[k + 8];
                    float x3 = A[k + 12] + Ee[k + 12];
                    best = fmaxf(best, fmaxf(fmaxf(x0, x1), fmaxf(x2, x3)));
                }
                for (; k < w2; k += 4)
                    best = fmaxf(best, A[k] + Ee[k]);
            }
            best = fmaxf(best, __shfl_xor_sync(FULLMASK, best, 1));
            best = fmaxf(best, __shfl_xor_sync(FULLMASK, best, 2));
            if (j < 128 && q == 0) {
                float v = best + P[S * i + j];
                R[S * i + w2] = v;
                E[S * j + 127 - w2] = v;
            }
        }
        __syncthreads();                    // phase boundary
    }

    // deterministic gold reduction: 64 per-block partials for this batch
    if (t < 32) {
        float g = g_goldpart[b * 64 + t] + g_goldpart[b * 64 + 32 + t];
        #pragma unroll
        for (int off = 16; off; off >>= 1)
            g += __shfl_xor_sync(FULLMASK, g, off);
        if (t == 0) {
            float pred = R[len - 1];        // betaS[0][len-1]
            g_margin[b] = fmaxf(pred - g, 0.0f);
        }
    }
}

// ---------------------------------------------------------------------------
// Kernel 3: mean over batches.
// ---------------------------------------------------------------------------
__global__ void mean_kernel(float* __restrict__ out) {
    int t = threadIdx.x;                    // 32 threads
    float v = g_margin[t] + g_margin[t + 32];
    #pragma unroll
    for (int off = 16; off; off >>= 1)
        v += __shfl_xor_sync(FULLMASK, v, off);
    if (t == 0) out[0] = v * (1.0f / 64.0f);
}

// ---------------------------------------------------------------------------
extern "C" void kernel_launch(void* const* d_in, const int* in_sizes, int n_in,
                              void* d_out, int out_size) {
    const float* logits = (const float*)d_in[0];   // [64,128,128,32] f32
    const int* labels   = (const int*)d_in[1];     // [64,128,128] int32
    float* out = (float*)d_out;

    (void)in_sizes; (void)n_in; (void)out_size;

    const int CKY_SMEM = 3 * 128 * 132 * (int)sizeof(float); // 202752 B
    cudaFuncSetAttribute(cky_kernel,
                         cudaFuncAttributeMaxDynamicSharedMemorySize, CKY_SMEM);

    pot_kernel<<<4096, 256>>>(logits, labels);
    cky_kernel<<<64, 512, CKY_SMEM>>>(logits, labels);
    mean_kernel<<<1, 32>>>(out);
}

// round 10
// speedup vs baseline: 1.3436x; 1.3436x over previous
#include <cuda_runtime.h>

#define NEGF (-1000000000.0f)
#define FULLMASK 0xffffffffu

// Scratch (device globals — no allocation allowed)
__device__ float g_pot[64 * 128 * 128];   // 4 MB: label/augment-maxed span potentials
__device__ float g_goldpart[4096];        // per-block gold partials (64 blocks per batch)
__device__ float g_margin[64];            // per-batch relu(pred - gold)

// ---------------------------------------------------------------------------
// Kernel 1: pot + gold partials. Warp-staged, shuffle-free.
// Each warp owns 32 consecutive cells (4KB contiguous gmem):
//   stage: 8 independent coalesced LDG.128 -> padded SMEM (cell stride 36
//          floats = 144B, 16B-aligned for LDS/STS.128)
//   reduce: each thread reads ITS cell (8 conflict-free LDS.128) and does the
//           full 32-way max + gold select in registers. No shuffles.
// Banks/phase: STS word = 36c + 4(l&7) -> 8 distinct 4-bank groups; LDS word
// = 36l + 4ch -> banks 4l+4ch distinct per phase. Conflict-free both ways.
// ---------------------------------------------------------------------------
__global__ void pot_kernel(const float* __restrict__ logits,
                           const int* __restrict__ labels) {
    __shared__ float stage[8 * 32 * 36];    // 8 warps x 32 cells x 36 floats
    __shared__ float gred[256];

    int t = threadIdx.x;
    int lane = t & 31;
    int warp = t >> 5;
    int cellbase = blockIdx.x * 256 + warp * 32;   // warp's first cell

    const float4* src = reinterpret_cast<const float4*>(logits)
                      + (size_t)cellbase * 8;
    float* st = stage + warp * (32 * 36);

    // stage 4KB: 8 independent LDG.128 (front-batched -> MLP 8)
    float4 f0 = src[0 * 32 + lane];
    float4 f1 = src[1 * 32 + lane];
    float4 f2 = src[2 * 32 + lane];
    float4 f3 = src[3 * 32 + lane];
    float4 f4 = src[4 * 32 + lane];
    float4 f5 = src[5 * 32 + lane];
    float4 f6 = src[6 * 32 + lane];
    float4 f7 = src[7 * 32 + lane];
    {
        float4 fr[8] = {f0, f1, f2, f3, f4, f5, f6, f7};
        #pragma unroll
        for (int m = 0; m < 8; ++m) {
            int g = m * 128 + lane * 4;     // float offset within warp's 4KB
            int c = g >> 5, wo = g & 31;    // cell, word-in-cell
            *reinterpret_cast<float4*>(st + c * 36 + wo) = fr[m];
        }
    }
    __syncwarp();

    int lab = labels[cellbase + lane];      // coalesced
    if (lab < 0) lab = 0;                   // jnp.maximum(labels, 0)

    // read own cell: 8 conflict-free LDS.128
    float q[32];
    #pragma unroll
    for (int ch = 0; ch < 8; ++ch) {
        float4 f = *reinterpret_cast<const float4*>(st + lane * 36 + ch * 4);
        q[ch * 4 + 0] = f.x; q[ch * 4 + 1] = f.y;
        q[ch * 4 + 2] = f.z; q[ch * 4 + 3] = f.w;
    }
    float v0 = q[0];
    float acc = NEGF, vl = 0.0f;
    #pragma unroll
    for (int l = 0; l < 32; ++l) {
        float x = (l == lab) ? q[l] : (q[l] + 1.0f);
        acc = fmaxf(acc, x);
        vl = (l == lab) ? q[l] : vl;
    }
    g_pot[cellbase + lane] = acc - v0;      // fully coalesced

    // deterministic block-reduce of gold contributions
    gred[t] = vl - v0;
    __syncthreads();
    #pragma unroll
    for (int s = 128; s >= 32; s >>= 1) {
        if (t < s) gred[t] += gred[t + s];
        __syncthreads();
    }
    if (t < 32) {
        float g = gred[t];
        #pragma unroll
        for (int off = 16; off; off >>= 1)
            g += __shfl_xor_sync(FULLMASK, g, off);
        if (t == 0) g_goldpart[blockIdx.x] = g;
    }
}

// ---------------------------------------------------------------------------
// Kernel 2: CKY max-plus inside pass (R5 version, known 58us). One CTA per
// batch, 512 threads: 4 lanes (q=0..3) per row i = t/4. Row stride S=132.
//   betaS[i][w]      at R[S*i + w]
//   betaE[j][127-w]  at E[S*j + 127 - w]
// Step w, row i, j=i+w:  best = max_{k<w} R[S*i+k] + E[S*j + 128-w + k]
// Lane q covers k = q, q+4, ... (uniform trips). Banks (132i + k) mod 32 =
// (4i + q + 4n) mod 32 -> 8 rows x 4 q = all 32 banks, conflict-free.
// ---------------------------------------------------------------------------
extern __shared__ float cky_smem[];

__global__ void cky_kernel(const float* __restrict__ logits,
                           const int* __restrict__ labels) {
    const int S = 132;
    float* R = cky_smem;                    // betaS: 128*S
    float* E = cky_smem + 128 * S;          // betaE: 128*S
    float* P = cky_smem + 256 * S;          // pot:   128*S
    __shared__ float sh_potfix;

    int b = blockIdx.x;
    int t = threadIdx.x;
    int i = t >> 2;                         // row 0..127
    int q = t & 3;                          // lane within row group
    int bcell = b * 16384;

    // length: count labels[b,0,j] != -100 (first 128 threads contribute)
    int haslab = (t < 128) ? (labels[bcell + t] != -100) : 0;
    int len = __syncthreads_count(haslab);

    // preload pot into SMEM (coalesced, conflict-free)
    for (int idx = t; idx < 16384; idx += 512)
        P[(idx >> 7) * S + (idx & 127)] = g_pot[bcell + idx];

    // recompute the augmented special cell (b, 0, len-1): channel 0 gets -1e9
    if (t < 32) {
        int j = len - 1;
        int lab = labels[bcell + j];
        if (lab < 0) lab = 0;
        float v = logits[(size_t)(bcell + j) * 32 + t];
        float x = (t == lab) ? v : (v + 1.0f);
        if (t == 0) x += NEGF;
        #pragma unroll
        for (int off = 16; off; off >>= 1)
            x = fmaxf(x, __shfl_xor_sync(FULLMASK, x, off));
        float v0 = __shfl_sync(FULLMASK, v, 0);
        if (t == 0) sh_potfix = x - v0;
    }
    __syncthreads();
    if (t == 0) P[len - 1] = sh_potfix;     // row 0, col len-1
    __syncthreads();

    // width-0 init (diagonal)
    if (q == 0) {
        float d = P[i * S + i];
        R[i * S] = d;                       // betaS[i][0]
        E[i * S + 127] = d;                 // betaE[i][127]
    }

    for (int w = 1; w < 128; ++w) {
        __syncthreads();                    // step w-1 writes visible
        int j = i + w;
        float best = NEGF;
        if (j < 128) {
            const float* A  = R + S * i;
            const float* Ee = E + S * j + (128 - w);
            int k = q;
            for (; k + 12 < w; k += 16) {   // 4x unroll: 8 batched LDS
                float x0 = A[k]      + Ee[k];
                float x1 = A[k + 4]  + Ee[k + 4];
                float x2 = A[k + 8]  + Ee[k + 8];
                float x3 = A[k + 12] + Ee[k + 12];
                best = fmaxf(best, fmaxf(fmaxf(x0, x1), fmaxf(x2, x3)));
            }
            for (; k < w; k += 4)
                best = fmaxf(best, A[k] + Ee[k]);
        }
        // all 512 threads reach these uniformly
        best = fmaxf(best, __shfl_xor_sync(FULLMASK, best, 1));
        best = fmaxf(best, __shfl_xor_sync(FULLMASK, best, 2));
        if (j < 128 && q == 0) {
            float v = best + P[S * i + i + w];
            R[S * i + w] = v;               // betaS[i][w]
            E[S * j + 127 - w] = v;         // betaE[j][127-w]
        }
    }
    __syncthreads();

    // deterministic gold reduction: 64 per-block partials for this batch
    if (t < 32) {
        float g = g_goldpart[b * 64 + t] + g_goldpart[b * 64 + 32 + t];
        #pragma unroll
        for (int off = 16; off; off >>= 1)
            g += __shfl_xor_sync(FULLMASK, g, off);
        if (t == 0) {
            float pred = R[len - 1];        // betaS[0][len-1]
            g_margin[b] = fmaxf(pred - g, 0.0f);
        }
    }
}

// ---------------------------------------------------------------------------
// Kernel 3: mean over batches.
// ---------------------------------------------------------------------------
__global__ void mean_kernel(float* __restrict__ out) {
    int t = threadIdx.x;                    // 32 threads
    float v = g_margin[t] + g_margin[t + 32];
    #pragma unroll
    for (int off = 16; off; off >>= 1)
        v += __shfl_xor_sync(FULLMASK, v, off);
    if (t == 0) out[0] = v * (1.0f / 64.0f);
}

// ---------------------------------------------------------------------------
extern "C" void kernel_launch(void* const* d_in, const int* in_sizes, int n_in,
                              void* d_out, int out_size) {
    const float* logits = (const float*)d_in[0];   // [64,128,128,32] f32
    const int* labels   = (const int*)d_in[1];     // [64,128,128] int32
    float* out = (float*)d_out;

    (void)in_sizes; (void)n_in; (void)out_size;

    const int CKY_SMEM = 3 * 128 * 132 * (int)sizeof(float); // 202752 B
    cudaFuncSetAttribute(cky_kernel,
                         cudaFuncAttributeMaxDynamicSharedMemorySize, CKY_SMEM);

    pot_kernel<<<4096, 256>>>(logits, labels);
    cky_kernel<<<64, 512, CKY_SMEM>>>(logits, labels);
    mean_kernel<<<1, 32>>>(out);
}